// round 10
// baseline (speedup 1.0000x reference)
#include <cuda_runtime.h>
#include <cstdint>

// FWHT of 4096-wide rows, sign flip + 2^-6 normalization.
// TWO ROWS PER CTA packed in f32x2 lanes (add.rn.f32x2 / fma.rn.f32x2):
// halves per-row butterfly issue. Persistent CTAs (3/SM), dynamic pair
// scheduling (global atomic), single-buffer TMA pipeline (32 KB / pair).
//
// Index plan per row (i = position, t = thread):
//   Round 1: i = 1024g + 4t + c     regs {c0,c1,g0,g1} -> strides 1,2,1024,2048
//   Round 2: regs j = i[5:2]                           -> strides 4,8,16,32
//   Round 3: regs k = i[9:6]                           -> strides 64..512
//
// Exchange 1 (pitch 18 f2, keyed by reader): writer 16x STS.64 (banks
//   2c + 8(l>>4) + (l&15), distinct per half-warp), reader 8x LDS.128
//   (16B banks t+q mod 8, distinct).
// Exchange 2 (pitch 20 f2, keyed by reader; FIXED from R9's non-injective
//   column map): value k of reader-row R lives at col 2*((k>>1)^((R>>1)&3))
//   + (k&1). Writer: addr = 20*R0 + 80j + col(j&1), two bases + imm (banks
//   4b + 2*((k0>>1)^m) + (k0&1), enumerated all-distinct per half-warp).
//   Reader: 8x LDS.128 at quad p = kq ^ ((t>>1)&3) (16B banks 2t + p mod 8,
//   pairwise distinct per 8-lane phase).

#define FWHT_D 4096

__device__ int g_pair_ctr;

// ---------- f32x2 helpers ----------
__device__ __forceinline__ unsigned long long f2pack(float lo, float hi)
{
    unsigned long long d;
    asm("mov.b64 %0, {%1, %2};" : "=l"(d) : "f"(lo), "f"(hi));
    return d;
}
__device__ __forceinline__ void f2unpack(unsigned long long d, float& lo, float& hi)
{
    asm("mov.b64 {%0, %1}, %2;" : "=f"(lo), "=f"(hi) : "l"(d));
}
__device__ __forceinline__ unsigned long long f2add(unsigned long long a, unsigned long long b)
{
    unsigned long long r;
    asm("add.rn.f32x2 %0, %1, %2;" : "=l"(r) : "l"(a), "l"(b));
    return r;
}
// a - b == fma(b, -1, a): (-1)*b exact, single rounding -> identical to FADD
__device__ __forceinline__ unsigned long long f2sub(unsigned long long a, unsigned long long b)
{
    const unsigned long long NEG1 = 0xBF800000BF800000ULL;
    unsigned long long r;
    asm("fma.rn.f32x2 %0, %1, %2, %3;" : "=l"(r) : "l"(b), "l"(NEG1), "l"(a));
    return r;
}

__device__ __forceinline__ uint32_t smem_u32(const void* p)
{
    uint32_t a;
    asm("{ .reg .u64 tmp; cvta.to.shared.u64 tmp, %1; cvt.u32.u64 %0, tmp; }"
        : "=r"(a) : "l"(p));
    return a;
}

__device__ __forceinline__ void mbar_wait(uint32_t mb, uint32_t parity)
{
    uint32_t done;
    asm volatile(
        "{\n\t.reg .pred p;\n\t"
        "mbarrier.try_wait.parity.acquire.cta.shared::cta.b64 p, [%1], %2;\n\t"
        "selp.b32 %0, 1, 0, p;\n\t}"
        : "=r"(done) : "r"(mb), "r"(parity) : "memory");
    if (!done) {
        asm volatile(
            "{\n\t.reg .pred P1;\n\t"
            "WL_%=:\n\t"
            "mbarrier.try_wait.parity.acquire.cta.shared::cta.b64 P1, [%0], %1, 0x989680;\n\t"
            "@P1 bra.uni WD_%=;\n\t"
            "bra.uni WL_%=;\n\t"
            "WD_%=:\n\t}"
            :: "r"(mb), "r"(parity) : "memory");
    }
}

__device__ __forceinline__ void tma_pair(uint32_t dst, const float* src, uint32_t mb)
{
    asm volatile("mbarrier.arrive.expect_tx.shared.b64 _, [%0], %1;"
                 :: "r"(mb), "r"((unsigned)(2 * FWHT_D * 4)) : "memory");
    asm volatile(
        "cp.async.bulk.shared::cta.global.mbarrier::complete_tx::bytes "
        "[%0], [%1], %2, [%3];"
        :: "r"(dst), "l"(src), "r"((unsigned)(2 * FWHT_D * 4)), "r"(mb)
        : "memory");
}

__device__ __forceinline__ void h16p(unsigned long long (&r)[16])
{
    #pragma unroll
    for (int p = 1; p < 16; p <<= 1) {
        #pragma unroll
        for (int k = 0; k < 16; ++k) {
            if ((k & p) == 0) {
                const unsigned long long a = r[k];
                const unsigned long long b = r[k | p];
                r[k]     = f2add(a, b);
                r[k | p] = f2sub(a, b);
            }
        }
    }
}

// dynamic smem layout (bytes):
//   [0, 32768)        in_buf: 2 rows fp32
//   [32768, 73728)    ex: 5120 f2 (ex1 uses pitch 18: 4608 f2; ex2 pitch 20: 5120 f2)
//   [73728, 73736)    mbarrier
#define SMEM_BYTES 73744

__global__ __launch_bounds__(256, 3) void RHTRotation_82394652607202_kernel(
    const float* __restrict__ x,
    const float* __restrict__ signs,
    float* __restrict__ out,
    int npairs)
{
    extern __shared__ __align__(128) char smem_raw[];
    float* in_buf          = reinterpret_cast<float*>(smem_raw);
    unsigned long long* ex = reinterpret_cast<unsigned long long*>(smem_raw + 32768);
    uint64_t* mbar         = reinterpret_cast<uint64_t*>(smem_raw + 73728);
    __shared__ int sh_pair;

    const int t = threadIdx.x;                         // 0..255
    const uint32_t mb  = smem_u32(mbar);
    const uint32_t ibf = smem_u32(in_buf);

    // ---- prologue: init mbar, draw first pair, start DMA ASAP ----
    if (t == 0) {
        asm volatile("mbarrier.init.shared.b64 [%0], %1;" :: "r"(mb), "r"(1));
        asm volatile("fence.proxy.async.shared::cta;" ::: "memory");
    }
    __syncthreads();
    if (t == 0) {
        const int p0 = atomicAdd(&g_pair_ctr, 1);
        sh_pair = p0;
        if (p0 < npairs)
            tma_pair(ibf, x + (long long)p0 * (2 * FWHT_D), mb);
    }

    // ---- loop-invariant: signs * 4096^-0.5 (overlaps first DMA) ----
    const float scale = 0.015625f;
    float sc[16];
    #pragma unroll
    for (int g = 0; g < 4; ++g) {
        const float4 s = *reinterpret_cast<const float4*>(signs + g * 1024 + t * 4);
        sc[g * 4 + 0] = s.x * scale;
        sc[g * 4 + 1] = s.y * scale;
        sc[g * 4 + 2] = s.z * scale;
        sc[g * 4 + 3] = s.w * scale;
    }

    // ---- loop-invariant exchange bases ----
    // ex1 write: row = c + 4*(t>>4) + 64g, col = t&15 (pitch 18)
    const int e1w = (t >> 4) * 72 + (t & 15);
    // ex2 write: R0 = (t&3) + 64*(t>>6); k0 = (t>>2)&15; e0 = (t>>1)&1
    //   col(j even) = 2*((k0>>1) ^ e0)       + (k0&1)
    //   col(j odd ) = 2*((k0>>1) ^ e0 ^ 2)   + (k0&1)
    const int k0  = (t >> 2) & 15;
    const int e0  = (t >> 1) & 1;
    const int R0  = (t & 3) + 64 * (t >> 6);
    const int ce  = 2 * ((k0 >> 1) ^ e0)     + (k0 & 1);
    const int co  = 2 * ((k0 >> 1) ^ e0 ^ 2) + (k0 & 1);
    unsigned long long* const w2e = ex + 20 * R0 + ce;
    unsigned long long* const w2o = ex + 20 * R0 + co;
    // ex2 read: mask for quad swizzle
    const int rmask = (t >> 1) & 3;
    const unsigned long long* const r2 = ex + 20 * t;

    __syncthreads();
    int pair = sh_pair;
    uint32_t parity = 0;

    const float4* in4 = reinterpret_cast<const float4*>(in_buf);

    while (pair < npairs) {
        // ---- wait for this pair's DMA ----
        mbar_wait(mb, parity);
        parity ^= 1;

        // ---- gather both rows, apply sign*scale, pack into f32x2 ----
        unsigned long long r[16];
        #pragma unroll
        for (int g = 0; g < 4; ++g) {
            const float4 a = in4[g * 256 + t];          // row A: i = 1024g+4t+c
            const float4 b = in4[1024 + g * 256 + t];   // row B
            r[g * 4 + 0] = f2pack(a.x * sc[g * 4 + 0], b.x * sc[g * 4 + 0]);
            r[g * 4 + 1] = f2pack(a.y * sc[g * 4 + 1], b.y * sc[g * 4 + 1]);
            r[g * 4 + 2] = f2pack(a.z * sc[g * 4 + 2], b.z * sc[g * 4 + 2]);
            r[g * 4 + 3] = f2pack(a.w * sc[g * 4 + 3], b.w * sc[g * 4 + 3]);
        }
        __syncthreads();   // in_buf free AND prior iteration's ex2 reads done

        // ---- draw next pair, prefetch (overlaps all compute below) ----
        if (t == 0) {
            const int nn = atomicAdd(&g_pair_ctr, 1);
            sh_pair = nn;
            if (nn < npairs)
                tma_pair(ibf, x + (long long)nn * (2 * FWHT_D), mb);
        }

        // ---- round 1: strides 1,2,1024,2048 ----
        h16p(r);

        // ---- exchange 1 write: 16x STS.64, addr = e1w + 1152g + 18c ----
        #pragma unroll
        for (int g = 0; g < 4; ++g)
            #pragma unroll
            for (int c = 0; c < 4; ++c)
                ex[e1w + g * 1152 + c * 18] = r[g * 4 + c];
        __syncthreads();

        // ---- exchange 1 read: row t (pitch 18), 8x LDS.128 ----
        {
            const ulonglong2* rp = reinterpret_cast<const ulonglong2*>(ex + t * 18);
            #pragma unroll
            for (int q = 0; q < 8; ++q) {
                const ulonglong2 v = rp[q];
                r[2 * q + 0] = v.x;
                r[2 * q + 1] = v.y;
            }
        }

        // ---- round 2: strides 4,8,16,32 ----
        h16p(r);

        __syncthreads();   // ex buffer reuse (pitch 18 -> pitch 20)

        // ---- exchange 2 write: value j -> row R0+4j, col(j&1); imm 80j ----
        #pragma unroll
        for (int j = 0; j < 16; ++j) {
            if (j & 1) w2o[80 * j] = r[j];
            else       w2e[80 * j] = r[j];
        }
        __syncthreads();

        const int next_pair = sh_pair;

        // ---- exchange 2 read: 8x LDS.128 at quad p = kq ^ rmask ----
        #pragma unroll
        for (int kq = 0; kq < 8; ++kq) {
            const int p = kq ^ rmask;
            const ulonglong2 v = *reinterpret_cast<const ulonglong2*>(r2 + 2 * p);
            r[2 * kq + 0] = v.x;
            r[2 * kq + 1] = v.y;
        }

        // ---- round 3: strides 64,128,256,512 ----
        h16p(r);

        // ---- store: unpack, i = (t>>6)*1024 + k*64 + (t&63), coalesced ----
        {
            float* opa = out + (long long)pair * (2 * FWHT_D) + (t >> 6) * 1024 + (t & 63);
            float* opb = opa + FWHT_D;
            #pragma unroll
            for (int k = 0; k < 16; ++k) {
                float lo, hi;
                f2unpack(r[k], lo, hi);
                opa[k * 64] = lo;
                opb[k * 64] = hi;
            }
        }

        pair = next_pair;
    }
}

extern "C" void kernel_launch(void* const* d_in, const int* in_sizes, int n_in,
                              void* d_out, int out_size)
{
    const float* a = (const float*)d_in[0];
    const float* b = (const float*)d_in[1];
    const float* x;
    const float* signs;
    if (in_sizes[0] == FWHT_D && in_sizes[1] > FWHT_D) { signs = a; x = b; }
    else                                               { x = a; signs = b; }

    const int rows   = out_size / FWHT_D;
    const int npairs = rows / 2;

    // Reset the dynamic-scheduling counter (graph-capturable async memset).
    void* ctr_addr = nullptr;
    cudaGetSymbolAddress(&ctr_addr, g_pair_ctr);
    cudaMemsetAsync(ctr_addr, 0, sizeof(int));

    cudaFuncSetAttribute(RHTRotation_82394652607202_kernel,
                         cudaFuncAttributeMaxDynamicSharedMemorySize, SMEM_BYTES);

    int grid = 3 * 148;                 // 3 CTAs/SM (73.7 KB smem), persistent
    if (grid > npairs) grid = npairs;
    RHTRotation_82394652607202_kernel<<<grid, 256, SMEM_BYTES>>>(
        x, signs, (float*)d_out, npairs);
}

// round 11
// speedup vs baseline: 1.0145x; 1.0145x over previous
#include <cuda_runtime.h>
#include <cstdint>

// FWHT of 4096-wide rows, sign flip + 2^-6 normalization.
// R7 kernel (best verified: 38.9us ncu, rel_err 1.2e-7) + SELF-RESETTING
// work-stealing counter: the last CTA to finish resets g_row_ctr/g_done,
// removing the cudaMemsetAsync graph node (single-node graph, smaller
// replay overhead). Persistent CTAs (5/SM), dynamic row scheduling,
// single-buffer TMA pipeline (prefetch next row after the gather barrier).
//
// Butterfly structure (verified):
//   Round 1: i = g*1024 + t*4 + c   regs {1,0,11,10} -> strides 1,2,1024,2048
//   Round 2: regs j = i[5:2]                         -> strides 4,8,16,32
//   Round 3: regs k = i[9:6]                         -> strides 64..512
// Exchange 1: pitch-20 rows keyed by reader (scalar STS imm / 4x LDS.128).
// Exchange 2: pitch-24 rows keyed by writer, quad slots XOR (t&4)
//             (4x STS.128 / scalar LDS imm, two bases).

#define FWHT_D 4096

__device__ int g_row_ctr;   // work-stealing ticket counter (self-reset)
__device__ int g_done_ctr;  // finished-CTA counter (self-reset)

__device__ __forceinline__ uint32_t smem_u32(const void* p)
{
    uint32_t a;
    asm("{ .reg .u64 tmp; cvta.to.shared.u64 tmp, %1; cvt.u32.u64 %0, tmp; }"
        : "=r"(a) : "l"(p));
    return a;
}

__device__ __forceinline__ void mbar_wait(uint32_t mb, uint32_t parity)
{
    uint32_t done;
    asm volatile(
        "{\n\t.reg .pred p;\n\t"
        "mbarrier.try_wait.parity.acquire.cta.shared::cta.b64 p, [%1], %2;\n\t"
        "selp.b32 %0, 1, 0, p;\n\t}"
        : "=r"(done) : "r"(mb), "r"(parity) : "memory");
    if (!done) {
        asm volatile(
            "{\n\t.reg .pred P1;\n\t"
            "WL_%=:\n\t"
            "mbarrier.try_wait.parity.acquire.cta.shared::cta.b64 P1, [%0], %1, 0x989680;\n\t"
            "@P1 bra.uni WD_%=;\n\t"
            "bra.uni WL_%=;\n\t"
            "WD_%=:\n\t}"
            :: "r"(mb), "r"(parity) : "memory");
    }
}

__device__ __forceinline__ void tma_row(uint32_t dst, const float* src, uint32_t mb)
{
    asm volatile("mbarrier.arrive.expect_tx.shared.b64 _, [%0], %1;"
                 :: "r"(mb), "r"((unsigned)(FWHT_D * 4)) : "memory");
    asm volatile(
        "cp.async.bulk.shared::cta.global.mbarrier::complete_tx::bytes "
        "[%0], [%1], %2, [%3];"
        :: "r"(dst), "l"(src), "r"((unsigned)(FWHT_D * 4)), "r"(mb)
        : "memory");
}

__device__ __forceinline__ void h16(float (&r)[16])
{
    #pragma unroll
    for (int p = 1; p < 16; p <<= 1) {
        #pragma unroll
        for (int k = 0; k < 16; ++k) {
            if ((k & p) == 0) {
                const float a = r[k];
                const float b = r[k | p];
                r[k]     = a + b;
                r[k | p] = a - b;
            }
        }
    }
}

__global__ __launch_bounds__(256, 5) void RHTRotation_82394652607202_kernel(
    const float* __restrict__ x,
    const float* __restrict__ signs,
    float* __restrict__ out,
    int rows)
{
    __shared__ __align__(128) float in_buf[FWHT_D];   // 16 KB TMA landing
    __shared__ __align__(128) float ex[6144];         // 24 KB exchange buffer
    __shared__ __align__(8)   uint64_t mbar;
    __shared__ int sh_row;

    const int t = threadIdx.x;                         // 0..255
    const uint32_t mb  = smem_u32(&mbar);
    const uint32_t ibf = smem_u32(in_buf);

    // ---- prologue: init mbar, draw first row, launch its DMA ASAP ----
    if (t == 0) {
        asm volatile("mbarrier.init.shared.b64 [%0], %1;" :: "r"(mb), "r"(1));
        asm volatile("fence.proxy.async.shared::cta;" ::: "memory");
    }
    __syncthreads();
    if (t == 0) {
        const int r0 = atomicAdd(&g_row_ctr, 1);
        sh_row = r0;
        if (r0 < rows)
            tma_row(ibf, x + (long long)r0 * FWHT_D, mb);
    }

    // ---- loop-invariant: signs * 4096^-0.5 (overlaps first DMA) ----
    const float scale = 0.015625f;
    float sc[16];
    #pragma unroll
    for (int g = 0; g < 4; ++g) {
        const float4 s = *reinterpret_cast<const float4*>(signs + g * 1024 + t * 4);
        sc[g * 4 + 0] = s.x * scale;
        sc[g * 4 + 1] = s.y * scale;
        sc[g * 4 + 2] = s.z * scale;
        sc[g * 4 + 3] = s.w * scale;
    }

    __syncthreads();                       // publish sh_row
    int cur = sh_row;

    uint32_t parity = 0;

    while (cur < rows) {
        // ---- wait for this row's DMA ----
        mbar_wait(mb, parity);
        parity ^= 1;

        // ---- gather row into registers (4x LDS.128, conflict-free) ----
        float r[16];
        #pragma unroll
        for (int g = 0; g < 4; ++g) {
            const float4 v = *reinterpret_cast<const float4*>(in_buf + g * 1024 + t * 4);
            r[g * 4 + 0] = v.x * sc[g * 4 + 0];
            r[g * 4 + 1] = v.y * sc[g * 4 + 1];
            r[g * 4 + 2] = v.z * sc[g * 4 + 2];
            r[g * 4 + 3] = v.w * sc[g * 4 + 3];
        }
        __syncthreads();          // everyone done reading in_buf

        // ---- draw next row, prefetch into the same buffer (overlaps compute) ----
        if (t == 0) {
            const int nxt = atomicAdd(&g_row_ctr, 1);
            sh_row = nxt;
            if (nxt < rows)
                tma_row(ibf, x + (long long)nxt * FWHT_D, mb);
        }

        // ---- round 1: strides 1,2,1024,2048 ----
        h16(r);

        // ---- exchange 1 write: addr = g*1280 + (t>>4)*80 + c*20 + (t&15) ----
        {
            const int base = (t >> 4) * 80 + (t & 15);
            #pragma unroll
            for (int g = 0; g < 4; ++g)
                #pragma unroll
                for (int c = 0; c < 4; ++c)
                    ex[base + g * 1280 + c * 20] = r[g * 4 + c];
        }
        __syncthreads();          // ex1 ready; also publishes sh_row

        const int nxt_row = sh_row;

        // ---- exchange 1 read: row t, 4x LDS.128 ----
        {
            const float* rp = ex + t * 20;
            #pragma unroll
            for (int q = 0; q < 4; ++q) {
                const float4 v = *reinterpret_cast<const float4*>(rp + 4 * q);
                r[q * 4 + 0] = v.x; r[q * 4 + 1] = v.y;
                r[q * 4 + 2] = v.z; r[q * 4 + 3] = v.w;
            }
        }

        // ---- round 2: strides 4,8,16,32 ----
        h16(r);

        __syncthreads();          // ex buffer reuse

        // ---- exchange 2 write: row t, pitch 24, quad slot (4q ^ (t&4)) ----
        {
            const int c4 = t & 4;
            float* wp = ex + t * 24;
            #pragma unroll
            for (int q = 0; q < 4; ++q) {
                *reinterpret_cast<float4*>(wp + ((4 * q) ^ c4)) =
                    make_float4(r[q * 4 + 0], r[q * 4 + 1], r[q * 4 + 2], r[q * 4 + 3]);
            }
        }
        __syncthreads();

        // ---- exchange 2 read: addr = A + k*96 + (B or B^4) ----
        {
            const int A  = (t >> 6) * 1536 + (t & 3) * 24;
            const int B  = (t >> 2) & 15;
            const int be = A + B;
            const int bo = A + (B ^ 4);
            #pragma unroll
            for (int k = 0; k < 16; ++k)
                r[k] = ex[((k & 1) ? bo : be) + k * 96];
        }

        // ---- round 3: strides 64,128,256,512 ----
        h16(r);

        // ---- store: i = (t>>6)*1024 + k*64 + (t&63), 128B/instr ----
        {
            float* op = out + (long long)cur * FWHT_D + (t >> 6) * 1024 + (t & 63);
            #pragma unroll
            for (int k = 0; k < 16; ++k)
                op[k * 64] = r[k];
        }

        cur = nxt_row;
    }

    // ---- self-reset of the scheduling counters (last-CTA protocol) ----
    // Every CTA reaches here after its final (>= rows) ticket draw. The
    // CTA whose done-ticket is last resets both counters for the next
    // graph replay. Fences order each CTA's g_row_ctr adds before its
    // g_done add, and the resets before kernel end.
    if (t == 0) {
        __threadfence();
        const int d = atomicAdd(&g_done_ctr, 1);
        if (d == (int)gridDim.x - 1) {
            g_row_ctr  = 0;
            g_done_ctr = 0;
            __threadfence();
        }
    }
}

extern "C" void kernel_launch(void* const* d_in, const int* in_sizes, int n_in,
                              void* d_out, int out_size)
{
    const float* a = (const float*)d_in[0];
    const float* b = (const float*)d_in[1];
    const float* x;
    const float* signs;
    if (in_sizes[0] == FWHT_D && in_sizes[1] > FWHT_D) { signs = a; x = b; }
    else                                               { x = a; signs = b; }

    const int rows = out_size / FWHT_D;

    int grid = 5 * 148;                 // 5 CTAs/SM, persistent, work-stealing
    if (grid > rows) grid = rows;
    RHTRotation_82394652607202_kernel<<<grid, 256>>>(x, signs, (float*)d_out, rows);
}

// round 12
// speedup vs baseline: 1.0447x; 1.0298x over previous
#include <cuda_runtime.h>
#include <cstdint>

// FWHT of 4096-wide rows, sign flip + 2^-6 normalization.
// Best-measured configuration (R7): persistent CTAs (5/SM) with dynamic row
// scheduling via a global atomic counter (self-balancing work stealing),
// single-buffer TMA pipeline — after the current row is gathered into
// registers (CTA barrier), the next row index is drawn and its
// cp.async.bulk issued into the same buffer, overlapping DMA with
// compute+store. Counter reset via cudaMemsetAsync graph node.
//
// At 38.9us kernel time this moves 268 MB => 6.9 TB/s aggregate R+W,
// ~85-90% of the practical HBM3e mixed-stream ceiling: memory-wall bound.
//
// Butterfly structure (verified, rel_err 1.216e-7):
//   Round 1: i = g*1024 + t*4 + c   regs {1,0,11,10} -> strides 1,2,1024,2048
//   Round 2: regs j = i[5:2]                         -> strides 4,8,16,32
//   Round 3: regs k = i[9:6]                         -> strides 64..512
// Exchange 1: pitch-20 rows keyed by reader (scalar STS imm / 4x LDS.128).
// Exchange 2: pitch-24 rows keyed by writer, quad slots XOR (t&4)
//             (4x STS.128 / scalar LDS imm, two bases) — pitch 24 is the
//             unique conflict-free pitch for this reader pattern
//             (24r mod 32 = {0,24,16,8} tiles the four 8-bank blocks).
// All 4 __syncthreads guard real hazards (buffer-free for TMA reissue, ex1
// w->r, ex buffer reuse, ex2 w->r); removing any reintroduces the R8 race.

#define FWHT_D 4096

__device__ int g_row_ctr;

__device__ __forceinline__ uint32_t smem_u32(const void* p)
{
    uint32_t a;
    asm("{ .reg .u64 tmp; cvta.to.shared.u64 tmp, %1; cvt.u32.u64 %0, tmp; }"
        : "=r"(a) : "l"(p));
    return a;
}

__device__ __forceinline__ void mbar_wait(uint32_t mb, uint32_t parity)
{
    uint32_t done;
    asm volatile(
        "{\n\t.reg .pred p;\n\t"
        "mbarrier.try_wait.parity.acquire.cta.shared::cta.b64 p, [%1], %2;\n\t"
        "selp.b32 %0, 1, 0, p;\n\t}"
        : "=r"(done) : "r"(mb), "r"(parity) : "memory");
    if (!done) {
        asm volatile(
            "{\n\t.reg .pred P1;\n\t"
            "WL_%=:\n\t"
            "mbarrier.try_wait.parity.acquire.cta.shared::cta.b64 P1, [%0], %1, 0x989680;\n\t"
            "@P1 bra.uni WD_%=;\n\t"
            "bra.uni WL_%=;\n\t"
            "WD_%=:\n\t}"
            :: "r"(mb), "r"(parity) : "memory");
    }
}

__device__ __forceinline__ void tma_row(uint32_t dst, const float* src, uint32_t mb)
{
    asm volatile("mbarrier.arrive.expect_tx.shared.b64 _, [%0], %1;"
                 :: "r"(mb), "r"((unsigned)(FWHT_D * 4)) : "memory");
    asm volatile(
        "cp.async.bulk.shared::cta.global.mbarrier::complete_tx::bytes "
        "[%0], [%1], %2, [%3];"
        :: "r"(dst), "l"(src), "r"((unsigned)(FWHT_D * 4)), "r"(mb)
        : "memory");
}

__device__ __forceinline__ void h16(float (&r)[16])
{
    #pragma unroll
    for (int p = 1; p < 16; p <<= 1) {
        #pragma unroll
        for (int k = 0; k < 16; ++k) {
            if ((k & p) == 0) {
                const float a = r[k];
                const float b = r[k | p];
                r[k]     = a + b;
                r[k | p] = a - b;
            }
        }
    }
}

__global__ __launch_bounds__(256, 5) void RHTRotation_82394652607202_kernel(
    const float* __restrict__ x,
    const float* __restrict__ signs,
    float* __restrict__ out,
    int rows)
{
    __shared__ __align__(128) float in_buf[FWHT_D];   // 16 KB TMA landing
    __shared__ __align__(128) float ex[6144];         // 24 KB exchange buffer
    __shared__ __align__(8)   uint64_t mbar;
    __shared__ int sh_row;

    const int t = threadIdx.x;                         // 0..255
    const uint32_t mb  = smem_u32(&mbar);
    const uint32_t ibf = smem_u32(in_buf);

    // ---- prologue: init mbar, draw first row, launch its DMA ASAP ----
    if (t == 0) {
        asm volatile("mbarrier.init.shared.b64 [%0], %1;" :: "r"(mb), "r"(1));
        asm volatile("fence.proxy.async.shared::cta;" ::: "memory");
    }
    __syncthreads();
    if (t == 0) {
        const int r0 = atomicAdd(&g_row_ctr, 1);
        sh_row = r0;
        if (r0 < rows)
            tma_row(ibf, x + (long long)r0 * FWHT_D, mb);
    }

    // ---- loop-invariant: signs * 4096^-0.5 (overlaps first DMA) ----
    const float scale = 0.015625f;
    float sc[16];
    #pragma unroll
    for (int g = 0; g < 4; ++g) {
        const float4 s = *reinterpret_cast<const float4*>(signs + g * 1024 + t * 4);
        sc[g * 4 + 0] = s.x * scale;
        sc[g * 4 + 1] = s.y * scale;
        sc[g * 4 + 2] = s.z * scale;
        sc[g * 4 + 3] = s.w * scale;
    }

    __syncthreads();                       // publish sh_row
    int cur = sh_row;

    uint32_t parity = 0;

    while (cur < rows) {
        // ---- wait for this row's DMA (the pacing point at the mem wall) ----
        mbar_wait(mb, parity);
        parity ^= 1;

        // ---- gather row into registers (4x LDS.128, conflict-free) ----
        float r[16];
        #pragma unroll
        for (int g = 0; g < 4; ++g) {
            const float4 v = *reinterpret_cast<const float4*>(in_buf + g * 1024 + t * 4);
            r[g * 4 + 0] = v.x * sc[g * 4 + 0];
            r[g * 4 + 1] = v.y * sc[g * 4 + 1];
            r[g * 4 + 2] = v.z * sc[g * 4 + 2];
            r[g * 4 + 3] = v.w * sc[g * 4 + 3];
        }
        __syncthreads();          // everyone done reading in_buf
                                  // (also: prior iter's ex2 reads all done)

        // ---- draw next row, prefetch into the same buffer (overlaps compute) ----
        if (t == 0) {
            const int nxt = atomicAdd(&g_row_ctr, 1);
            sh_row = nxt;
            if (nxt < rows)
                tma_row(ibf, x + (long long)nxt * FWHT_D, mb);
        }

        // ---- round 1: strides 1,2,1024,2048 ----
        h16(r);

        // ---- exchange 1 write: addr = g*1280 + (t>>4)*80 + c*20 + (t&15) ----
        {
            const int base = (t >> 4) * 80 + (t & 15);
            #pragma unroll
            for (int g = 0; g < 4; ++g)
                #pragma unroll
                for (int c = 0; c < 4; ++c)
                    ex[base + g * 1280 + c * 20] = r[g * 4 + c];
        }
        __syncthreads();          // ex1 ready; also publishes sh_row

        const int nxt_row = sh_row;

        // ---- exchange 1 read: row t, 4x LDS.128 ----
        {
            const float* rp = ex + t * 20;
            #pragma unroll
            for (int q = 0; q < 4; ++q) {
                const float4 v = *reinterpret_cast<const float4*>(rp + 4 * q);
                r[q * 4 + 0] = v.x; r[q * 4 + 1] = v.y;
                r[q * 4 + 2] = v.z; r[q * 4 + 3] = v.w;
            }
        }

        // ---- round 2: strides 4,8,16,32 ----
        h16(r);

        __syncthreads();          // ex buffer reuse (pitch 20 -> pitch 24)

        // ---- exchange 2 write: row t, pitch 24, quad slot (4q ^ (t&4)) ----
        {
            const int c4 = t & 4;
            float* wp = ex + t * 24;
            #pragma unroll
            for (int q = 0; q < 4; ++q) {
                *reinterpret_cast<float4*>(wp + ((4 * q) ^ c4)) =
                    make_float4(r[q * 4 + 0], r[q * 4 + 1], r[q * 4 + 2], r[q * 4 + 3]);
            }
        }
        __syncthreads();

        // ---- exchange 2 read: addr = A + k*96 + (B or B^4) ----
        {
            const int A  = (t >> 6) * 1536 + (t & 3) * 24;
            const int B  = (t >> 2) & 15;
            const int be = A + B;
            const int bo = A + (B ^ 4);
            #pragma unroll
            for (int k = 0; k < 16; ++k)
                r[k] = ex[((k & 1) ? bo : be) + k * 96];
        }

        // ---- round 3: strides 64,128,256,512 ----
        h16(r);

        // ---- store: i = (t>>6)*1024 + k*64 + (t&63), 128B/instr ----
        {
            float* op = out + (long long)cur * FWHT_D + (t >> 6) * 1024 + (t & 63);
            #pragma unroll
            for (int k = 0; k < 16; ++k)
                op[k * 64] = r[k];
        }

        cur = nxt_row;
    }
}

extern "C" void kernel_launch(void* const* d_in, const int* in_sizes, int n_in,
                              void* d_out, int out_size)
{
    const float* a = (const float*)d_in[0];
    const float* b = (const float*)d_in[1];
    const float* x;
    const float* signs;
    if (in_sizes[0] == FWHT_D && in_sizes[1] > FWHT_D) { signs = a; x = b; }
    else                                               { x = a; signs = b; }

    const int rows = out_size / FWHT_D;

    // Reset the dynamic-scheduling counter (graph-capturable async memset).
    void* ctr_addr = nullptr;
    cudaGetSymbolAddress(&ctr_addr, g_row_ctr);
    cudaMemsetAsync(ctr_addr, 0, sizeof(int));

    int grid = 5 * 148;                 // 5 CTAs/SM, persistent, work-stealing
    if (grid > rows) grid = rows;
    RHTRotation_82394652607202_kernel<<<grid, 256>>>(x, signs, (float*)d_out, rows);
}